// round 15
// baseline (speedup 1.0000x reference)
#include <cuda_runtime.h>

typedef unsigned long long u64;

#define NT 512
#define GRID_BLKS 129   // 1 chain + 128 conv

// ---- chain smem (floats): slot s at s*SLOT: rm 64x68 @0, dup 64x132 @4352 ----
#define SLOT  12800
#define DUPO  4352
#define CH_SV 25600     // 2 x 64 s-vectors
// ---- conv smem (floats) ----
#define C_W1S 0          // 64 x 168
#define C_XS  10752      // 3 x 8 x 72
#define C_HA  12480      // 64 x 132
#define C_HB  20928      // 64 x 132
#define H0_LD 132
#define C_ADS 29376      // 64 x 128
#define C_SAS 37568      // 64
#define C_B1S 37632      // 64
#define SMEM_FLOATS 37696

__device__ float g_AD[3][8192];   // phase p: dup layout [c][2*o] of P_{8,64,128}
__device__ float g_sA[3][64];
__device__ int   g_flag[3][32];   // one 128B line per phase
__device__ int   g_done[32];

__device__ __forceinline__ u64 pk2(float a, float b) {
    u64 r; asm("mov.b64 %0, {%1, %2};" : "=l"(r) : "f"(a), "f"(b)); return r;
}
__device__ __forceinline__ float2 up2(u64 v) {
    float2 r; asm("mov.b64 {%0, %1}, %2;" : "=f"(r.x), "=f"(r.y) : "l"(v)); return r;
}
__device__ __forceinline__ void fma2(u64& d, u64 a, u64 b) {
    asm("fma.rn.f32x2 %0, %1, %2, %0;" : "+l"(d) : "l"(a), "l"(b));
}

__global__ void __launch_bounds__(NT, 1)
fused(const float* __restrict__ x, const float* __restrict__ W1,
      const float* __restrict__ b1, const float* __restrict__ W2,
      const float* __restrict__ b2, float* __restrict__ out)
{
    extern __shared__ float sm[];
    const int t   = threadIdx.x;
    const int bid = blockIdx.x;

    if (bid == 0) {
        // ========== chain block: 7 squarings, dup-layout compose ==========
        for (int i = t; i < 4096; i += NT) {
            int r = i >> 6, c = i & 63;
            float v = W2[i];
            sm[r * 68 + c] = v;                                      // rm0
            *(float2*)&sm[DUPO + c * 132 + 2 * r] = make_float2(v, v); // dup0
        }
        if (t < 64) sm[CH_SV + t] = b2[t];
        __syncthreads();

        const int w = t >> 5, lane = t & 31;
        const int r0 = w * 4;        // 16 warps x 4 rows
        const int c0 = lane * 2;     // 32 lanes x 2 cols

        int cur = 0;
#pragma unroll 1
        for (int s = 0; s < 7; ++s) {
            const int nxt = cur ^ 1;
            const float* crm  = sm + cur * SLOT;
            const float* cdup = sm + cur * SLOT + DUPO;
            float* nrm  = sm + nxt * SLOT;
            float* ndup = sm + nxt * SLOT + DUPO;
            const float* svc = sm + CH_SV + cur * 64;
            float* svn = sm + CH_SV + nxt * 64;

            u64 acc0 = 0, acc1 = 0, acc2 = 0, acc3 = 0;
            const float* ap = cdup + 2 * r0;   // uniform across warp
            const float* bp = crm + c0;
#pragma unroll 8
            for (int k = 0; k < 64; ++k) {
                ulonglong2 a01 = *(const ulonglong2*)ap;        // rows r0,r0+1 (dup)
                ulonglong2 a23 = *(const ulonglong2*)(ap + 4);  // rows r0+2,r0+3
                u64 b = *(const u64*)bp;                        // B[k][c0..c0+1]
                fma2(acc0, a01.x, b);
                fma2(acc1, a01.y, b);
                fma2(acc2, a23.x, b);
                fma2(acc3, a23.y, b);
                ap += 132; bp += 68;
            }
            // row-major stores
            *(u64*)(nrm + (r0 + 0) * 68 + c0) = acc0;
            *(u64*)(nrm + (r0 + 1) * 68 + c0) = acc1;
            *(u64*)(nrm + (r0 + 2) * 68 + c0) = acc2;
            *(u64*)(nrm + (r0 + 3) * 68 + c0) = acc3;
            // dup stores (transposed, duplicated pairs)
            {
                float2 e0 = up2(acc0), e1 = up2(acc1), e2 = up2(acc2), e3 = up2(acc3);
                *(float4*)(ndup + c0 * 132 + 2 * r0)           = make_float4(e0.x, e0.x, e1.x, e1.x);
                *(float4*)(ndup + c0 * 132 + 2 * r0 + 4)       = make_float4(e2.x, e2.x, e3.x, e3.x);
                *(float4*)(ndup + (c0 + 1) * 132 + 2 * r0)     = make_float4(e0.y, e0.y, e1.y, e1.y);
                *(float4*)(ndup + (c0 + 1) * 132 + 2 * r0 + 4) = make_float4(e2.y, e2.y, e3.y, e3.y);
            }
            // s' = P*s + s  (P[r][k] = cdup[k*132 + 2r])
            if (t < 64) {
                float ss = svc[t];
#pragma unroll 8
                for (int k = 0; k < 64; ++k)
                    ss = fmaf(cdup[k * 132 + 2 * t], svc[k], ss);
                svn[t] = ss;
            }
            __syncthreads();
            cur = nxt;

            // publish milestones T8 (s=2), T64 (s=5), T128 (s=6): direct dup copy
            if (s == 2 || s == 5 || s == 6) {
                const int p = (s == 2) ? 0 : (s == 5) ? 1 : 2;
                const float* pdup = sm + cur * SLOT + DUPO;
                for (int i = t; i < 2048; i += NT) {
                    int c = i >> 5, j = i & 31;
                    *(float4*)&g_AD[p][c * 128 + 4 * j] =
                        *(const float4*)&pdup[c * 132 + 4 * j];
                }
                if (t < 64) g_sA[p][t] = sm[CH_SV + cur * 64 + t];
                __threadfence();
                __syncthreads();
                if (t == 0) atomicExch(&g_flag[p][0], 1);
            }
        }
    } else {
        // ========== conv + 3-phase apply blocks (R11-proven) ==========
        float* W1s = sm + C_W1S;
        float* xs  = sm + C_XS;
        float* hA  = sm + C_HA;
        float* hB  = sm + C_HB;
        float* ADs = sm + C_ADS;
        float* sAs = sm + C_SAS;
        float* b1s = sm + C_B1S;

        const int r0b = (bid - 1) * 2;
        const int bb = r0b >> 6, y0 = r0b & 63;   // both rows in same image

        for (int i = t; i < 10752; i += NT) {
            int m = i / 168, jp = i % 168;
            int ii = jp / 56, r = jp % 56, ky = r / 8, kx = r % 8;
            W1s[i] = (kx < 7) ? W1[m * 147 + ii * 49 + ky * 7 + kx] : 0.0f;
        }
        if (t < 64) b1s[t] = b1[t];
        for (int i = t; i < 1728; i += NT) {
            int ii = i / 576, rem = i % 576;
            int yy = rem / 72, xx = rem % 72;
            xs[i] = (xx < 70) ? x[((bb * 3 + ii) * 70 + (y0 + yy)) * 70 + xx] : 0.0f;
        }
        __syncthreads();

        // ---- conv: hA = conv7x7(x, W1) + b1, 2 rows paired in f32x2 ----
        const int xq = t & 7, oc = t >> 3;
        const int x0 = xq * 8;

        u64 acc[8];
        {
            u64 bv = pk2(b1s[oc], b1s[oc]);
#pragma unroll
            for (int xi = 0; xi < 8; ++xi) acc[xi] = bv;
        }

#pragma unroll 1
        for (int ii = 0; ii < 3; ++ii) {
#pragma unroll 1
            for (int ky = 0; ky < 7; ++ky) {
                const float* p0 = xs + (ii * 8 + ky) * 72 + x0;
                const float* p1 = p0 + 72;
                float a0[16], a1[16];
#pragma unroll
                for (int q = 0; q < 4; ++q) {
                    float4 u = *(const float4*)(p0 + q * 4);
                    a0[q*4+0] = u.x; a0[q*4+1] = u.y; a0[q*4+2] = u.z; a0[q*4+3] = u.w;
                    float4 v = *(const float4*)(p1 + q * 4);
                    a1[q*4+0] = v.x; a1[q*4+1] = v.y; a1[q*4+2] = v.z; a1[q*4+3] = v.w;
                }
                u64 xwp[14];
#pragma unroll
                for (int i = 0; i < 14; ++i) xwp[i] = pk2(a0[i], a1[i]);

                const float* wq = W1s + oc * 168 + ii * 56 + ky * 8;
                float4 w0 = *(const float4*)(wq);
                float4 w1 = *(const float4*)(wq + 4);
                u64 wp[7];
                wp[0] = pk2(w0.x, w0.x); wp[1] = pk2(w0.y, w0.y);
                wp[2] = pk2(w0.z, w0.z); wp[3] = pk2(w0.w, w0.w);
                wp[4] = pk2(w1.x, w1.x); wp[5] = pk2(w1.y, w1.y);
                wp[6] = pk2(w1.z, w1.z);
#pragma unroll
                for (int kx = 0; kx < 7; ++kx)
#pragma unroll
                    for (int xi = 0; xi < 8; ++xi)
                        fma2(acc[xi], wp[kx], xwp[kx + xi]);
            }
        }

        {   // hA[c][px], px = row*64 + x
            float2 v[8];
#pragma unroll
            for (int xi = 0; xi < 8; ++xi) v[xi] = up2(acc[xi]);
            float* hb = hA + oc * H0_LD;
            *(float4*)(hb + x0)          = make_float4(v[0].x, v[1].x, v[2].x, v[3].x);
            *(float4*)(hb + x0 + 4)      = make_float4(v[4].x, v[5].x, v[6].x, v[7].x);
            *(float4*)(hb + 64 + x0)     = make_float4(v[0].y, v[1].y, v[2].y, v[3].y);
            *(float4*)(hb + 64 + x0 + 4) = make_float4(v[4].y, v[5].y, v[6].y, v[7].y);
        }
        __syncthreads();

        // ---- 3 affine applies: T8, T64, T128 (exponents add) ----
        const int og = (t >> 4) & 15, pq = t & 15;
        const int o0 = og * 4, px0 = pq * 8;
        const int rr = px0 >> 6, xx0 = px0 & 63, yy = y0 + rr;
        const bool act = (t < 256);

#pragma unroll 1
        for (int p = 0; p < 3; ++p) {
            if (t == 0) {
                while (atomicAdd(&g_flag[p][0], 0) == 0) __nanosleep(128);
            }
            __syncthreads();
            for (int i = t; i < 2048; i += NT)
                *(float4*)(ADs + 4 * i) = __ldcg((const float4*)g_AD[p] + i);
            if (t < 64) sAs[t] = __ldcg(&g_sA[p][t]);
            __syncthreads();

            const float* hin = (p & 1) ? hB : hA;
            float* hout      = (p & 1) ? hA : hB;

            if (act) {
                u64 ap2[4][4] = {};
#pragma unroll 4
                for (int c = 0; c < 64; ++c) {
                    const float* adp = ADs + c * 128 + 8 * og;
                    ulonglong2 ad0 = *(const ulonglong2*)(adp);
                    ulonglong2 ad1 = *(const ulonglong2*)(adp + 4);
                    ulonglong2 hv0 = *(const ulonglong2*)(hin + c * H0_LD + px0);
                    ulonglong2 hv1 = *(const ulonglong2*)(hin + c * H0_LD + px0 + 4);
                    fma2(ap2[0][0], ad0.x, hv0.x); fma2(ap2[0][1], ad0.x, hv0.y);
                    fma2(ap2[0][2], ad0.x, hv1.x); fma2(ap2[0][3], ad0.x, hv1.y);
                    fma2(ap2[1][0], ad0.y, hv0.x); fma2(ap2[1][1], ad0.y, hv0.y);
                    fma2(ap2[1][2], ad0.y, hv1.x); fma2(ap2[1][3], ad0.y, hv1.y);
                    fma2(ap2[2][0], ad1.x, hv0.x); fma2(ap2[2][1], ad1.x, hv0.y);
                    fma2(ap2[2][2], ad1.x, hv1.x); fma2(ap2[2][3], ad1.x, hv1.y);
                    fma2(ap2[3][0], ad1.y, hv0.x); fma2(ap2[3][1], ad1.y, hv0.y);
                    fma2(ap2[3][2], ad1.y, hv1.x); fma2(ap2[3][3], ad1.y, hv1.y);
                }
#pragma unroll
                for (int j = 0; j < 4; ++j) {
                    const int o = o0 + j;
                    const float sa = sAs[o];
                    float2 v0 = up2(ap2[j][0]), v1 = up2(ap2[j][1]);
                    float2 v2 = up2(ap2[j][2]), v3 = up2(ap2[j][3]);
                    if (p < 2) {
                        float* pd = hout + o * H0_LD + px0;
                        *(float4*)(pd)     = make_float4(v0.x + sa, v0.y + sa, v1.x + sa, v1.y + sa);
                        *(float4*)(pd + 4) = make_float4(v2.x + sa, v2.y + sa, v3.x + sa, v3.y + sa);
                    } else {
                        float* pd = out + ((bb * 64 + o) * 64 + yy) * 64 + xx0;
                        *(float4*)(pd)     = make_float4(v0.x + sa, v0.y + sa, v1.x + sa, v1.y + sa);
                        *(float4*)(pd + 4) = make_float4(v2.x + sa, v2.y + sa, v3.x + sa, v3.y + sa);
                    }
                }
            }
            __syncthreads();
        }
    }

    // ---- self-resetting counters for clean graph replays ----
    __syncthreads();
    if (t == 0) {
        __threadfence();
        int d = atomicAdd(&g_done[0], 1);
        if (d == GRID_BLKS - 1) {
            atomicExch(&g_flag[0][0], 0);
            atomicExch(&g_flag[1][0], 0);
            atomicExch(&g_flag[2][0], 0);
            atomicExch(&g_done[0], 0);
        }
    }
}

extern "C" void kernel_launch(void* const* d_in, const int* in_sizes, int n_in,
                              void* d_out, int out_size)
{
    (void)in_sizes; (void)n_in; (void)out_size;
    const float* x  = (const float*)d_in[0];
    const float* W1 = (const float*)d_in[1];
    const float* b1 = (const float*)d_in[2];
    const float* W2 = (const float*)d_in[3];
    const float* b2 = (const float*)d_in[4];
    float* out = (float*)d_out;

    const size_t smem = (size_t)SMEM_FLOATS * sizeof(float);
    cudaFuncSetAttribute(fused, cudaFuncAttributeMaxDynamicSharedMemorySize, (int)smem);
    fused<<<GRID_BLKS, NT, smem>>>(x, W1, b1, W2, b2, out);
}

// round 16
// speedup vs baseline: 1.1897x; 1.1897x over previous
#include <cuda_runtime.h>

typedef unsigned long long u64;

#define NT 512
#define GRID_BLKS 129   // 1 chain + 128 conv

// ---- chain smem (floats): slot s at s*8704 (rm 64x68 @0, MT 64x68 @4352) ----
#define CH_SV 17408     // 2 x 64 s-vectors
#define CH_SCR 17536    // 4096 merge scratch
// ---- conv smem (floats) ----
#define C_W1S 0          // 64 x 168
#define C_XS  10752      // 3 x 8 x 72
#define C_HA  12480      // 64 x 132
#define C_HB  20928      // 64 x 132
#define H0_LD 132
#define C_ADS 29376      // 64 x 128
#define C_SAS 37568      // 64
#define C_B1S 37632      // 64
#define SMEM_FLOATS 37696

__device__ float g_AD[3][8192];   // phase p: dup layout [c][2*o] of P_{8,64,128}
__device__ float g_sA[3][64];
__device__ int   g_flag[3][32];   // one 128B line per phase
__device__ int   g_done[32];

__device__ __forceinline__ u64 pk2(float a, float b) {
    u64 r; asm("mov.b64 %0, {%1, %2};" : "=l"(r) : "f"(a), "f"(b)); return r;
}
__device__ __forceinline__ float2 up2(u64 v) {
    float2 r; asm("mov.b64 {%0, %1}, %2;" : "=f"(r.x), "=f"(r.y) : "l"(v)); return r;
}
__device__ __forceinline__ void fma2(u64& d, u64 a, u64 b) {
    asm("fma.rn.f32x2 %0, %1, %2, %0;" : "+l"(d) : "l"(a), "l"(b));
}
__device__ __forceinline__ void fadd2(u64& d, u64 a) {
    asm("add.rn.f32x2 %0, %0, %1;" : "+l"(d) : "l"(a));
}

// ---------------------------------------------------------------------------
// Squaring compose (R5/R11-proven): T_{2n} = T_n o T_n.
// ---------------------------------------------------------------------------
__device__ __forceinline__ void compose_sq(float* sm, int cur, int nxt, int t)
{
    const float* AT  = sm + cur * 8704 + 4352;
    const float* Brm = sm + cur * 8704;
    float* Crm = sm + nxt * 8704;
    float* CT  = sm + nxt * 8704 + 4352;
    const float* svA = sm + CH_SV + cur * 64;
    float* svC = sm + CH_SV + nxt * 64;
    float* scr = sm + CH_SCR;

    const int w = t >> 5, lane = t & 31;
    const int h = w >> 3, tile = w & 7;
    const int rbase = (tile & 3) * 16, cbase = (tile >> 2) * 32;
    const int ro = lane >> 2, co = lane & 3;
    const int r0 = rbase + ro * 2, c0 = cbase + co * 8;

    u64 acc[2][4] = {};
    const float* aP = AT  + (h * 32) * 68 + r0;
    const float* bP = Brm + (h * 32) * 68 + c0;
#pragma unroll 4
    for (int kk = 0; kk < 32; ++kk) {
        float2 a = *(const float2*)aP;
        ulonglong2 b0 = *(const ulonglong2*)bP;
        ulonglong2 b1 = *(const ulonglong2*)(bP + 4);
        u64 d0 = pk2(a.x, a.x), d1 = pk2(a.y, a.y);
        fma2(acc[0][0], d0, b0.x); fma2(acc[0][1], d0, b0.y);
        fma2(acc[0][2], d0, b1.x); fma2(acc[0][3], d0, b1.y);
        fma2(acc[1][0], d1, b0.x); fma2(acc[1][1], d1, b0.y);
        fma2(acc[1][2], d1, b1.x); fma2(acc[1][3], d1, b1.y);
        aP += 68; bP += 68;
    }

    if (h == 1) {
        float* sp = scr + (tile * 32 + lane) * 4;
        ulonglong2 v;
        v.x = acc[0][0]; v.y = acc[0][1]; *(ulonglong2*)(sp)        = v;
        v.x = acc[0][2]; v.y = acc[0][3]; *(ulonglong2*)(sp + 1024) = v;
        v.x = acc[1][0]; v.y = acc[1][1]; *(ulonglong2*)(sp + 2048) = v;
        v.x = acc[1][2]; v.y = acc[1][3]; *(ulonglong2*)(sp + 3072) = v;
    }
    __syncthreads();
    if (h == 0) {
        const float* sp = scr + (tile * 32 + lane) * 4;
        ulonglong2 p0 = *(const ulonglong2*)(sp);
        ulonglong2 p1 = *(const ulonglong2*)(sp + 1024);
        ulonglong2 p2 = *(const ulonglong2*)(sp + 2048);
        ulonglong2 p3 = *(const ulonglong2*)(sp + 3072);
        fadd2(acc[0][0], p0.x); fadd2(acc[0][1], p0.y);
        fadd2(acc[0][2], p1.x); fadd2(acc[0][3], p1.y);
        fadd2(acc[1][0], p2.x); fadd2(acc[1][1], p2.y);
        fadd2(acc[1][2], p3.x); fadd2(acc[1][3], p3.y);
        ulonglong2 v;
        v.x = acc[0][0]; v.y = acc[0][1]; *(ulonglong2*)(Crm + r0 * 68 + c0)           = v;
        v.x = acc[0][2]; v.y = acc[0][3]; *(ulonglong2*)(Crm + r0 * 68 + c0 + 4)       = v;
        v.x = acc[1][0]; v.y = acc[1][1]; *(ulonglong2*)(Crm + (r0 + 1) * 68 + c0)     = v;
        v.x = acc[1][2]; v.y = acc[1][3]; *(ulonglong2*)(Crm + (r0 + 1) * 68 + c0 + 4) = v;
#pragma unroll
        for (int j = 0; j < 4; ++j) {
            float2 e0 = up2(acc[0][j]);
            float2 e1 = up2(acc[1][j]);
            float2 u;
            u.x = e0.x; u.y = e1.x; *(float2*)(CT + (c0 + 2 * j)     * 68 + r0) = u;
            u.x = e0.y; u.y = e1.y; *(float2*)(CT + (c0 + 2 * j + 1) * 68 + r0) = u;
        }
    } else if (t < 320) {
        const int r = t - 256;
        float s = svA[r];
#pragma unroll 8
        for (int k = 0; k < 64; ++k)
            s = fmaf(AT[k * 68 + r], svA[k], s);
        svC[r] = s;
    }
    __syncthreads();
}

__global__ void __launch_bounds__(NT, 1)
fused(const float* __restrict__ x, const float* __restrict__ W1,
      const float* __restrict__ b1, const float* __restrict__ W2,
      const float* __restrict__ b2, float* __restrict__ out)
{
    extern __shared__ float sm[];
    const int t   = threadIdx.x;
    const int bid = blockIdx.x;

    if (bid == 0) {
        // ========== chain block: 7 squarings, publish T8/T64/T128 ==========
        for (int i = t; i < 4096; i += NT) {
            int r = i >> 6, c = i & 63;
            float v = W2[i];
            sm[r * 68 + c]        = v;   // slot0 rm
            sm[4352 + c * 68 + r] = v;   // slot0 MT
        }
        if (t < 64) sm[CH_SV + t] = b2[t];
        __syncthreads();

        int cur = 0;
#pragma unroll 1
        for (int s = 0; s < 7; ++s) {
            const int nxt = cur ^ 1;
            compose_sq(sm, cur, nxt, t);
            cur = nxt;
            if (s == 2 || s == 5 || s == 6) {
                const int p = (s == 2) ? 0 : (s == 5) ? 1 : 2;
                const float* Pat = sm + cur * 8704 + 4352;
                for (int i = t; i < 4096; i += NT) {
                    int c = i >> 6, o = i & 63;
                    float v = Pat[c * 68 + o];   // = P[o][c]
                    *(float2*)(&g_AD[p][c * 128 + 2 * o]) = make_float2(v, v);
                }
                if (t < 64) g_sA[p][t] = sm[CH_SV + cur * 64 + t];
                __threadfence();
                __syncthreads();
                if (t == 0) atomicExch(&g_flag[p][0], 1);
            }
        }
    } else {
        // ========== conv + 3-phase apply blocks ==========
        float* W1s = sm + C_W1S;
        float* xs  = sm + C_XS;
        float* hA  = sm + C_HA;
        float* hB  = sm + C_HB;
        float* ADs = sm + C_ADS;
        float* sAs = sm + C_SAS;
        float* b1s = sm + C_B1S;

        const int r0b = (bid - 1) * 2;
        const int bb = r0b >> 6, y0 = r0b & 63;   // both rows in same image

        for (int i = t; i < 10752; i += NT) {
            int m = i / 168, jp = i % 168;
            int ii = jp / 56, r = jp % 56, ky = r / 8, kx = r % 8;
            W1s[i] = (kx < 7) ? W1[m * 147 + ii * 49 + ky * 7 + kx] : 0.0f;
        }
        if (t < 64) b1s[t] = b1[t];
        for (int i = t; i < 1728; i += NT) {
            int ii = i / 576, rem = i % 576;
            int yy = rem / 72, xx = rem % 72;
            xs[i] = (xx < 70) ? x[((bb * 3 + ii) * 70 + (y0 + yy)) * 70 + xx] : 0.0f;
        }
        __syncthreads();

        // ---- conv: hA = conv7x7(x, W1) + b1, 2 rows paired in f32x2 ----
        const int xq = t & 7, oc = t >> 3;
        const int x0 = xq * 8;

        u64 acc[8];
        {
            u64 bv = pk2(b1s[oc], b1s[oc]);
#pragma unroll
            for (int xi = 0; xi < 8; ++xi) acc[xi] = bv;
        }

#pragma unroll 1
        for (int ii = 0; ii < 3; ++ii) {
#pragma unroll 1
            for (int ky = 0; ky < 7; ++ky) {
                const float* p0 = xs + (ii * 8 + ky) * 72 + x0;
                const float* p1 = p0 + 72;
                float a0[16], a1[16];
#pragma unroll
                for (int q = 0; q < 4; ++q) {
                    float4 u = *(const float4*)(p0 + q * 4);
                    a0[q*4+0] = u.x; a0[q*4+1] = u.y; a0[q*4+2] = u.z; a0[q*4+3] = u.w;
                    float4 v = *(const float4*)(p1 + q * 4);
                    a1[q*4+0] = v.x; a1[q*4+1] = v.y; a1[q*4+2] = v.z; a1[q*4+3] = v.w;
                }
                u64 xwp[14];
#pragma unroll
                for (int i = 0; i < 14; ++i) xwp[i] = pk2(a0[i], a1[i]);

                const float* wq = W1s + oc * 168 + ii * 56 + ky * 8;
                float4 w0 = *(const float4*)(wq);
                float4 w1 = *(const float4*)(wq + 4);
                u64 wp[7];
                wp[0] = pk2(w0.x, w0.x); wp[1] = pk2(w0.y, w0.y);
                wp[2] = pk2(w0.z, w0.z); wp[3] = pk2(w0.w, w0.w);
                wp[4] = pk2(w1.x, w1.x); wp[5] = pk2(w1.y, w1.y);
                wp[6] = pk2(w1.z, w1.z);
#pragma unroll
                for (int kx = 0; kx < 7; ++kx)
#pragma unroll
                    for (int xi = 0; xi < 8; ++xi)
                        fma2(acc[xi], wp[kx], xwp[kx + xi]);
            }
        }

        {   // hA[c][px], px = row*64 + x
            float2 v[8];
#pragma unroll
            for (int xi = 0; xi < 8; ++xi) v[xi] = up2(acc[xi]);
            float* hb = hA + oc * H0_LD;
            *(float4*)(hb + x0)          = make_float4(v[0].x, v[1].x, v[2].x, v[3].x);
            *(float4*)(hb + x0 + 4)      = make_float4(v[4].x, v[5].x, v[6].x, v[7].x);
            *(float4*)(hb + 64 + x0)     = make_float4(v[0].y, v[1].y, v[2].y, v[3].y);
            *(float4*)(hb + 64 + x0 + 4) = make_float4(v[4].y, v[5].y, v[6].y, v[7].y);
        }
        __syncthreads();

        // ---- 3 affine applies: T8, T64, T128 (exponents add) ----
        // tiling: warp = 4 oc x 128 px (A warp-uniform); thread = 4 oc x 4 px
        const int w = t >> 5, lane = t & 31;
        const int o0 = w * 4;          // 16 warps x 4 oc = 64
        const int px0 = lane * 4;      // 32 lanes x 4 px = 128
        const int rr = px0 >> 6, xx0 = px0 & 63, yy = y0 + rr;

#pragma unroll 1
        for (int p = 0; p < 3; ++p) {
            if (t == 0) {
                while (atomicAdd(&g_flag[p][0], 0) == 0) __nanosleep(128);
            }
            __syncthreads();
            for (int i = t; i < 2048; i += NT)
                *(float4*)(ADs + 4 * i) = __ldcg((const float4*)g_AD[p] + i);
            if (t < 64) sAs[t] = __ldcg(&g_sA[p][t]);
            __syncthreads();

            const float* hin = (p & 1) ? hB : hA;
            float* hout      = (p & 1) ? hA : hB;

            u64 ac[4][2] = {};
#pragma unroll 4
            for (int c = 0; c < 64; ++c) {
                const float* adp = ADs + c * 128 + 2 * o0;     // warp-uniform
                ulonglong2 a01 = *(const ulonglong2*)(adp);     // dup(o0), dup(o0+1)
                ulonglong2 a23 = *(const ulonglong2*)(adp + 4); // dup(o0+2), dup(o0+3)
                ulonglong2 hv  = *(const ulonglong2*)(hin + c * H0_LD + px0);
                fma2(ac[0][0], a01.x, hv.x); fma2(ac[0][1], a01.x, hv.y);
                fma2(ac[1][0], a01.y, hv.x); fma2(ac[1][1], a01.y, hv.y);
                fma2(ac[2][0], a23.x, hv.x); fma2(ac[2][1], a23.x, hv.y);
                fma2(ac[3][0], a23.y, hv.x); fma2(ac[3][1], a23.y, hv.y);
            }

#pragma unroll
            for (int j = 0; j < 4; ++j) {
                const int o = o0 + j;
                const float sa = sAs[o];
                float2 v0 = up2(ac[j][0]), v1 = up2(ac[j][1]);
                float4 res = make_float4(v0.x + sa, v0.y + sa, v1.x + sa, v1.y + sa);
                if (p < 2) *(float4*)(hout + o * H0_LD + px0) = res;
                else       *(float4*)(out + ((bb * 64 + o) * 64 + yy) * 64 + xx0) = res;
            }
            __syncthreads();
        }
    }

    // ---- self-resetting counters for clean graph replays ----
    __syncthreads();
    if (t == 0) {
        __threadfence();
        int d = atomicAdd(&g_done[0], 1);
        if (d == GRID_BLKS - 1) {
            atomicExch(&g_flag[0][0], 0);
            atomicExch(&g_flag[1][0], 0);
            atomicExch(&g_flag[2][0], 0);
            atomicExch(&g_done[0], 0);
        }
    }
}

extern "C" void kernel_launch(void* const* d_in, const int* in_sizes, int n_in,
                              void* d_out, int out_size)
{
    (void)in_sizes; (void)n_in; (void)out_size;
    const float* x  = (const float*)d_in[0];
    const float* W1 = (const float*)d_in[1];
    const float* b1 = (const float*)d_in[2];
    const float* W2 = (const float*)d_in[3];
    const float* b2 = (const float*)d_in[4];
    float* out = (float*)d_out;

    const size_t smem = (size_t)SMEM_FLOATS * sizeof(float);
    cudaFuncSetAttribute(fused, cudaFuncAttributeMaxDynamicSharedMemorySize, (int)smem);
    fused<<<GRID_BLKS, NT, smem>>>(x, W1, b1, W2, b2, out);
}